// round 5
// baseline (speedup 1.0000x reference)
#include <cuda_runtime.h>

#define BATCH 16
#define NPTS  2048
#define CDIM  64
#define ODIM  64
#define KNN   20
#define ROWS_TOTAL (BATCH*NPTS)   // 32768
#define NEG_INF (-3.402823466e38f)
#define FULLMASK 0xffffffffu

typedef unsigned long long ull;

// packed f32x2 helpers (sm_100+; ptxas never emits FFMA2 from C++)
#define LDS_U64X2(a0, a1, addr) \
    asm("ld.shared.v2.u64 {%0,%1},[%2];" : "=l"(a0), "=l"(a1) : "r"(addr))
#define FMA2(d, a, b) \
    asm("fma.rn.f32x2 %0, %1, %2, %0;" : "+l"(d) : "l"(a), "l"(b))
#define UNPACK2(lo, hi, v) \
    asm("mov.b64 {%0,%1}, %2;" : "=f"(lo), "=f"(hi) : "l"(v))

// ---------------- scratch (static device globals; no allocation) ----------------
__device__ float  g_xx[ROWS_TOTAL];
__device__ float  g_hc[ROWS_TOTAL*ODIM];
__device__ float  g_hn[ROWS_TOTAL*ODIM];
__device__ int    g_idx[ROWS_TOTAL*KNN];
__device__ float  g_mmax[ROWS_TOTAL*ODIM];
__device__ float  g_mmin[ROWS_TOTAL*ODIM];
__device__ double g_sum[ODIM];
__device__ double g_sumsq[ODIM];
__device__ float  g_scale[ODIM];
__device__ float  g_shift[ODIM];

// ---------------- K0: zero stats accumulators (graph replay safe) ----------------
__global__ void k_zero() {
    int t = threadIdx.x;
    if (t < ODIM) { g_sum[t] = 0.0; g_sumsq[t] = 0.0; }
}

// ---------------- K1: row squared norms ----------------
__global__ void k_xx(const float* __restrict__ x) {
    int row  = blockIdx.x * 4 + (threadIdx.x >> 5);
    int lane = threadIdx.x & 31;
    const float2* x2 = (const float2*)(x + (size_t)row * CDIM);
    float2 v = x2[lane];
    float s = v.x * v.x + v.y * v.y;
    #pragma unroll
    for (int o = 16; o; o >>= 1) s += __shfl_down_sync(FULLMASK, s, o);
    if (lane == 0) g_xx[row] = s;
}

// ---------------- K2: hc = x@W1^T + b, hn = x@W2^T  (32 rows/block) ----------------
__global__ void k_hchn(const float* __restrict__ x, const float* __restrict__ W,
                       const float* __restrict__ bias) {
    extern __shared__ float sm[];
    float4* Wt4 = (float4*)sm;          // [128*17]
    float4* rX4 = Wt4 + 128 * 17;       // [32*16]
    int t = threadIdx.x;
    int rowbase = blockIdx.x * 32;
    const float4* Wg4 = (const float4*)W;
    const float4* xg4 = (const float4*)x;

    #pragma unroll 2
    for (int li = t; li < 128 * 16; li += 256) {
        int cq = li & 15, p = li >> 4;
        Wt4[p * 17 + cq] = (p < 64) ? Wg4[p * 32 + cq] : Wg4[(p - 64) * 32 + 16 + cq];
    }
    for (int li = t; li < 32 * 16; li += 256) {
        int cq = li & 15, r = li >> 4;
        rX4[r * 16 + cq] = xg4[(size_t)(rowbase + r) * 16 + cq];
    }
    __syncthreads();

    int warp = t >> 5, j = t & 31;
    int rl0 = warp * 4;
    float acc[4][4];
    #pragma unroll
    for (int r = 0; r < 4; r++)
        #pragma unroll
        for (int q = 0; q < 4; q++) acc[r][q] = 0.f;

    #pragma unroll
    for (int cq = 0; cq < 16; cq++) {
        float4 c0 = Wt4[(j     ) * 17 + cq];
        float4 c1 = Wt4[(j + 32) * 17 + cq];
        float4 c2 = Wt4[(j + 64) * 17 + cq];
        float4 c3 = Wt4[(j + 96) * 17 + cq];
        #pragma unroll
        for (int r = 0; r < 4; r++) {
            float4 rv = rX4[(rl0 + r) * 16 + cq];
            acc[r][0] = fmaf(rv.w, c0.w, fmaf(rv.z, c0.z, fmaf(rv.y, c0.y, fmaf(rv.x, c0.x, acc[r][0]))));
            acc[r][1] = fmaf(rv.w, c1.w, fmaf(rv.z, c1.z, fmaf(rv.y, c1.y, fmaf(rv.x, c1.x, acc[r][1]))));
            acc[r][2] = fmaf(rv.w, c2.w, fmaf(rv.z, c2.z, fmaf(rv.y, c2.y, fmaf(rv.x, c2.x, acc[r][2]))));
            acc[r][3] = fmaf(rv.w, c3.w, fmaf(rv.z, c3.z, fmaf(rv.y, c3.y, fmaf(rv.x, c3.x, acc[r][3]))));
        }
    }
    #pragma unroll
    for (int q = 0; q < 4; q++) {
        int p = j + 32 * q;
        float bv = (p < 64) ? bias[p] : 0.f;
        #pragma unroll
        for (int r = 0; r < 4; r++) {
            int row = rowbase + rl0 + r;
            if (p < 64) g_hc[(size_t)row * 64 + p] = acc[r][q] + bv;
            else        g_hn[(size_t)row * 64 + (p - 64)] = acc[r][q];
        }
    }
}

// ---------------- K3: fused Gram + top-20 per row ----------------
// 512 threads = 16 warps, 32 rows/block (2 rows/warp), col tiles of 128.
// GEMM inner product uses packed fma.rn.f32x2: accumulator halves hold
// even-k / odd-k partial sums; both operands are natural float2 pairs of the
// existing float4 tiles (no packing movs). dot = lo + hi at the end.
// Top-20 list distributed across lanes (lane j<20 holds element j, desc).
// Stale-threshold insert: th refreshed once per 32-candidate batch; a stale
// (lower) th only admits candidates whose insertion pos >= 20 (no-op writes).
__global__ void __launch_bounds__(512, 2) k_topk(const float* __restrict__ x) {
    extern __shared__ float sm[];
    float4* rX4  = (float4*)sm;              // [32*16]
    float4* cX4  = rX4 + 32 * 16;            // [128*17]
    float*  xxc  = (float*)(cX4 + 128 * 17); // [128]

    int t = threadIdx.x;
    int b = blockIdx.y;
    int rowbase = b * NPTS + blockIdx.x * 32;
    const float4* xg4 = (const float4*)x;

    for (int li = t; li < 32 * 16; li += 512) {
        int cq = li & 15, r = li >> 4;
        rX4[r * 16 + cq] = xg4[(size_t)(rowbase + r) * 16 + cq];
    }

    int warp = t >> 5, j = t & 31;
    int rl0 = warp * 2;
    bool inlist = (j < KNN);

    unsigned sbase = (unsigned)__cvta_generic_to_shared(sm);
    unsigned cbase = sbase + 32u * 16u * 16u;
    unsigned ca0 = cbase + (unsigned)((j      ) * 17) * 16u;
    unsigned ca1 = cbase + (unsigned)((j + 32) * 17) * 16u;
    unsigned ca2 = cbase + (unsigned)((j + 64) * 17) * 16u;
    unsigned ca3 = cbase + (unsigned)((j + 96) * 17) * 16u;
    unsigned ra0 = sbase + (unsigned)(rl0 * 16) * 16u;
    unsigned ra1 = ra0 + 256u;

    float lv[2]; int lidx[2]; float th[2];
    #pragma unroll
    for (int r = 0; r < 2; r++) { lv[r] = NEG_INF; lidx[r] = 0; th[r] = NEG_INF; }

    for (int ct = 0; ct < 16; ct++) {
        int cb = ct * 128;
        __syncthreads();
        #pragma unroll 2
        for (int li = t; li < 128 * 16; li += 512) {
            int cq = li & 15, col = li >> 4;
            cX4[col * 17 + cq] = xg4[(size_t)(b * NPTS + cb + col) * 16 + cq];
        }
        if (t < 128) xxc[t] = g_xx[b * NPTS + cb + t];
        __syncthreads();

        ull A[2][4];
        #pragma unroll
        for (int r = 0; r < 2; r++)
            #pragma unroll
            for (int q = 0; q < 4; q++) A[r][q] = 0ull;

        #pragma unroll
        for (int cq = 0; cq < 16; cq++) {
            unsigned off = (unsigned)cq * 16u;
            ull c0a, c0b, c1a, c1b, c2a, c2b, c3a, c3b, r0a, r0b, r1a, r1b;
            LDS_U64X2(c0a, c0b, ca0 + off);
            LDS_U64X2(c1a, c1b, ca1 + off);
            LDS_U64X2(c2a, c2b, ca2 + off);
            LDS_U64X2(c3a, c3b, ca3 + off);
            LDS_U64X2(r0a, r0b, ra0 + off);
            LDS_U64X2(r1a, r1b, ra1 + off);
            FMA2(A[0][0], c0a, r0a); FMA2(A[0][0], c0b, r0b);
            FMA2(A[0][1], c1a, r0a); FMA2(A[0][1], c1b, r0b);
            FMA2(A[0][2], c2a, r0a); FMA2(A[0][2], c2b, r0b);
            FMA2(A[0][3], c3a, r0a); FMA2(A[0][3], c3b, r0b);
            FMA2(A[1][0], c0a, r1a); FMA2(A[1][0], c0b, r1b);
            FMA2(A[1][1], c1a, r1a); FMA2(A[1][1], c1b, r1b);
            FMA2(A[1][2], c2a, r1a); FMA2(A[1][2], c2b, r1b);
            FMA2(A[1][3], c3a, r1a); FMA2(A[1][3], c3b, r1b);
        }

        float xq0 = xxc[j], xq1 = xxc[j + 32], xq2 = xxc[j + 64], xq3 = xxc[j + 96];

        #pragma unroll
        for (int r = 0; r < 2; r++) {
            float lo, hi;
            UNPACK2(lo, hi, A[r][0]);
            float cnd0 = fmaf(-2.f, hi, fmaf(-2.f, lo, xq0));
            UNPACK2(lo, hi, A[r][1]);
            float cnd1 = fmaf(-2.f, hi, fmaf(-2.f, lo, xq1));
            UNPACK2(lo, hi, A[r][2]);
            float cnd2 = fmaf(-2.f, hi, fmaf(-2.f, lo, xq2));
            UNPACK2(lo, hi, A[r][3]);
            float cnd3 = fmaf(-2.f, hi, fmaf(-2.f, lo, xq3));

            // row-tile prefilter: skip all 4 batches when nothing can pass
            float rmax = fmaxf(fmaxf(cnd0, cnd1), fmaxf(cnd2, cnd3));
            if (__ballot_sync(FULLMASK, rmax > th[r]) == 0u) continue;

            #pragma unroll
            for (int q = 0; q < 4; q++) {
                float cand = (q == 0) ? cnd0 : (q == 1) ? cnd1 : (q == 2) ? cnd2 : cnd3;
                int   col  = cb + j + 32 * q;
                unsigned mask = __ballot_sync(FULLMASK, cand > th[r]);
                while (mask) {
                    int src = __ffs(mask) - 1; mask &= mask - 1;
                    float val = __shfl_sync(FULLMASK, cand, src);
                    int   ci  = __shfl_sync(FULLMASK, col,  src);
                    // stable insertion: pos = #elements >= val; pos>=20 -> no-op
                    unsigned ge = __ballot_sync(FULLMASK, inlist && (lv[r] >= val));
                    int pos = __popc(ge);
                    float pv = __shfl_up_sync(FULLMASK, lv[r], 1);
                    int   pi = __shfl_up_sync(FULLMASK, lidx[r], 1);
                    if (inlist) {
                        if (j == pos)     { lv[r] = val; lidx[r] = ci; }
                        else if (j > pos) { lv[r] = pv;  lidx[r] = pi; }
                    }
                }
                th[r] = __shfl_sync(FULLMASK, lv[r], KNN - 1);
            }
        }
    }

    #pragma unroll
    for (int r = 0; r < 2; r++) {
        int row = rowbase + rl0 + r;
        if (inlist) g_idx[(size_t)row * KNN + j] = lidx[r];
    }
}

// ---------------- K4: gather + BN stats + per-(row,o) max/min ----------------
__global__ void k_stats() {
    __shared__ int   sidx[32 * KNN];
    __shared__ float ssum[4][64];
    __shared__ float sssq[4][64];
    int tx = threadIdx.x, ty = threadIdx.y;
    int t = ty * 64 + tx;
    int rowbase = blockIdx.x * 32;
    int bb = (rowbase >> 11) << 11;

    for (int i = t; i < 32 * KNN; i += 256) sidx[i] = g_idx[(size_t)rowbase * KNN + i];
    __syncthreads();

    float sum = 0.f, ssq = 0.f;
    for (int ri = ty; ri < 32; ri += 4) {
        int row = rowbase + ri;
        float hcv = g_hc[(size_t)row * 64 + tx];
        float mx = NEG_INF, mn = -NEG_INF;
        #pragma unroll
        for (int k = 0; k < KNN; k++) {
            int jj = sidx[ri * KNN + k];
            float v = hcv + g_hn[(size_t)(bb + jj) * 64 + tx];
            sum += v; ssq = fmaf(v, v, ssq);
            mx = fmaxf(mx, v); mn = fminf(mn, v);
        }
        g_mmax[(size_t)row * 64 + tx] = mx;
        g_mmin[(size_t)row * 64 + tx] = mn;
    }
    ssum[ty][tx] = sum; sssq[ty][tx] = ssq;
    __syncthreads();
    if (ty == 0) {
        float s = ssum[0][tx] + ssum[1][tx] + ssum[2][tx] + ssum[3][tx];
        float q = sssq[0][tx] + sssq[1][tx] + sssq[2][tx] + sssq[3][tx];
        atomicAdd(&g_sum[tx],   (double)s);
        atomicAdd(&g_sumsq[tx], (double)q);
    }
}

// ---------------- K5: finalize BN scale/shift ----------------
__global__ void k_final(const float* __restrict__ gamma, const float* __restrict__ beta) {
    int o = threadIdx.x;
    if (o < ODIM) {
        double cnt  = (double)ROWS_TOTAL * KNN;
        double mean = g_sum[o] / cnt;
        double var  = g_sumsq[o] / cnt - mean * mean;
        float sc = gamma[o] * rsqrtf((float)var + 1e-5f);
        g_scale[o] = sc;
        g_shift[o] = beta[o] - (float)mean * sc;
    }
}

// ---------------- K6: apply affine + LeakyReLU + transpose to [B,O,N] ----------------
__global__ void k_out(float* __restrict__ out) {
    __shared__ float smt[64][65];
    int tx = threadIdx.x, ty = threadIdx.y;   // block (64,4)
    int nb = blockIdx.x * 64;
    int b  = blockIdx.y;
    float sc = g_scale[tx], sh = g_shift[tx];
    #pragma unroll
    for (int i = 0; i < 16; i++) {
        int nl = ty + 4 * i;
        size_t rowoff = (size_t)(b * NPTS + nb + nl) * 64 + tx;
        float m = (sc >= 0.f) ? g_mmax[rowoff] : g_mmin[rowoff];
        float y = fmaf(m, sc, sh);
        y = (y >= 0.f) ? y : 0.2f * y;
        smt[nl][tx] = y;
    }
    __syncthreads();
    #pragma unroll
    for (int i = 0; i < 16; i++) {
        int o = ty + 4 * i;
        out[((size_t)(b * 64 + o)) * NPTS + nb + tx] = smt[tx][o];
    }
}

extern "C" void kernel_launch(void* const* d_in, const int* in_sizes, int n_in,
                              void* d_out, int out_size) {
    const float* x     = (const float*)d_in[0];
    const float* W     = (const float*)d_in[1];
    const float* bias  = (const float*)d_in[2];
    const float* gamma = (const float*)d_in[3];
    const float* beta  = (const float*)d_in[4];
    float* out = (float*)d_out;

    k_zero<<<1, 64>>>();
    k_xx<<<ROWS_TOTAL / 4, 128>>>(x);
    k_hchn<<<ROWS_TOTAL / 32, 256, (128 * 17 + 32 * 16) * 16>>>(x, W, bias);
    k_topk<<<dim3(NPTS / 32, BATCH), 512,
             (32 * 16 + 128 * 17) * 16 + 128 * 4>>>(x);
    k_stats<<<ROWS_TOTAL / 32, dim3(64, 4)>>>();
    k_final<<<1, 64>>>(gamma, beta);
    k_out<<<dim3(NPTS / 64, BATCH), dim3(64, 4)>>>(out);
}

// round 6
// speedup vs baseline: 1.0472x; 1.0472x over previous
#include <cuda_runtime.h>

#define BATCH 16
#define NPTS  2048
#define CDIM  64
#define ODIM  64
#define KNN   20
#define ROWS_TOTAL (BATCH*NPTS)   // 32768
#define NEG_INF (-3.402823466e38f)
#define FULLMASK 0xffffffffu

// ---------------- scratch (static device globals; no allocation) ----------------
__device__ float  g_xx[ROWS_TOTAL];
__device__ float  g_hc[ROWS_TOTAL*ODIM];
__device__ float  g_hn[ROWS_TOTAL*ODIM];
__device__ int    g_idx[ROWS_TOTAL*KNN];
__device__ float  g_mmax[ROWS_TOTAL*ODIM];
__device__ float  g_mmin[ROWS_TOTAL*ODIM];
__device__ double g_sum[ODIM];
__device__ double g_sumsq[ODIM];
__device__ float  g_scale[ODIM];
__device__ float  g_shift[ODIM];

// ---------------- K0: zero stats accumulators (graph replay safe) ----------------
__global__ void k_zero() {
    int t = threadIdx.x;
    if (t < ODIM) { g_sum[t] = 0.0; g_sumsq[t] = 0.0; }
}

// ---------------- K1: row squared norms ----------------
__global__ void k_xx(const float* __restrict__ x) {
    int row  = blockIdx.x * 4 + (threadIdx.x >> 5);
    int lane = threadIdx.x & 31;
    const float2* x2 = (const float2*)(x + (size_t)row * CDIM);
    float2 v = x2[lane];
    float s = v.x * v.x + v.y * v.y;
    #pragma unroll
    for (int o = 16; o; o >>= 1) s += __shfl_down_sync(FULLMASK, s, o);
    if (lane == 0) g_xx[row] = s;
}

// ---------------- K2: hc = x@W1^T + b, hn = x@W2^T  (32 rows/block) ----------------
__global__ void k_hchn(const float* __restrict__ x, const float* __restrict__ W,
                       const float* __restrict__ bias) {
    extern __shared__ float sm[];
    float4* Wt4 = (float4*)sm;          // [128*17]
    float4* rX4 = Wt4 + 128 * 17;       // [32*16]
    int t = threadIdx.x;
    int rowbase = blockIdx.x * 32;
    const float4* Wg4 = (const float4*)W;
    const float4* xg4 = (const float4*)x;

    #pragma unroll 2
    for (int li = t; li < 128 * 16; li += 256) {
        int cq = li & 15, p = li >> 4;
        Wt4[p * 17 + cq] = (p < 64) ? Wg4[p * 32 + cq] : Wg4[(p - 64) * 32 + 16 + cq];
    }
    for (int li = t; li < 32 * 16; li += 256) {
        int cq = li & 15, r = li >> 4;
        rX4[r * 16 + cq] = xg4[(size_t)(rowbase + r) * 16 + cq];
    }
    __syncthreads();

    int warp = t >> 5, j = t & 31;
    int rl0 = warp * 4;
    float acc[4][4];
    #pragma unroll
    for (int r = 0; r < 4; r++)
        #pragma unroll
        for (int q = 0; q < 4; q++) acc[r][q] = 0.f;

    #pragma unroll
    for (int cq = 0; cq < 16; cq++) {
        float4 c0 = Wt4[(j     ) * 17 + cq];
        float4 c1 = Wt4[(j + 32) * 17 + cq];
        float4 c2 = Wt4[(j + 64) * 17 + cq];
        float4 c3 = Wt4[(j + 96) * 17 + cq];
        #pragma unroll
        for (int r = 0; r < 4; r++) {
            float4 rv = rX4[(rl0 + r) * 16 + cq];
            acc[r][0] = fmaf(rv.w, c0.w, fmaf(rv.z, c0.z, fmaf(rv.y, c0.y, fmaf(rv.x, c0.x, acc[r][0]))));
            acc[r][1] = fmaf(rv.w, c1.w, fmaf(rv.z, c1.z, fmaf(rv.y, c1.y, fmaf(rv.x, c1.x, acc[r][1]))));
            acc[r][2] = fmaf(rv.w, c2.w, fmaf(rv.z, c2.z, fmaf(rv.y, c2.y, fmaf(rv.x, c2.x, acc[r][2]))));
            acc[r][3] = fmaf(rv.w, c3.w, fmaf(rv.z, c3.z, fmaf(rv.y, c3.y, fmaf(rv.x, c3.x, acc[r][3]))));
        }
    }
    #pragma unroll
    for (int q = 0; q < 4; q++) {
        int p = j + 32 * q;
        float bv = (p < 64) ? bias[p] : 0.f;
        #pragma unroll
        for (int r = 0; r < 4; r++) {
            int row = rowbase + rl0 + r;
            if (p < 64) g_hc[(size_t)row * 64 + p] = acc[r][q] + bv;
            else        g_hn[(size_t)row * 64 + (p - 64)] = acc[r][q];
        }
    }
}

// ---------------- K3: fused Gram + top-20 per row ----------------
// 256 threads = 8 warps, 64 rows/block (8 rows/warp), col tiles of 128.
// cX stored with XOR swizzle (cq ^ (col&15)) -> conflict-free phases, no pad,
// fits 48KB static SMEM. Row loads are warp-broadcast (1 wavefront each).
// k-summation order identical to R4 (numerics-stable for topk selection).
// Top-20 list distributed across lanes (lane j<20 holds element j, desc).
// Stale-threshold insert: thr refreshed once per 32-candidate batch; a stale
// (lower) thr only admits candidates whose insertion pos >= 20 (no-op writes).
__global__ void __launch_bounds__(256, 4) k_topk(const float* __restrict__ x) {
    __shared__ float4 rX4s[64 * 16];    // 16 KB
    __shared__ float4 cX4s[128 * 16];   // 32 KB (swizzled)

    int t = threadIdx.x;
    int b = blockIdx.y;
    int rowbase = b * NPTS + blockIdx.x * 64;
    const float4* xg4 = (const float4*)x;

    for (int li = t; li < 64 * 16; li += 256) {
        int cq = li & 15, r = li >> 4;
        rX4s[li] = xg4[(size_t)(rowbase + r) * 16 + cq];
    }

    int warp = t >> 5, j = t & 31;
    int rl0 = warp * 8;
    bool inlist = (j < KNN);
    int jm = j & 15;

    float lv[8]; int lidx[8];
    #pragma unroll
    for (int r = 0; r < 8; r++) { lv[r] = NEG_INF; lidx[r] = 0; }

    for (int ct = 0; ct < 16; ct++) {
        int cb = ct * 128;
        __syncthreads();
        #pragma unroll 2
        for (int li = t; li < 128 * 16; li += 256) {
            int cq = li & 15, col = li >> 4;
            cX4s[(col << 4) + (cq ^ (col & 15))] =
                xg4[(size_t)(b * NPTS + cb + col) * 16 + cq];
        }
        __syncthreads();

        float acc[8][4];
        #pragma unroll
        for (int r = 0; r < 8; r++)
            #pragma unroll
            for (int q = 0; q < 4; q++) acc[r][q] = 0.f;

        #pragma unroll 4
        for (int cq = 0; cq < 16; cq++) {
            int p = cq ^ jm;
            float4 c0 = cX4s[((j      ) << 4) + p];
            float4 c1 = cX4s[((j +  32) << 4) + p];
            float4 c2 = cX4s[((j +  64) << 4) + p];
            float4 c3 = cX4s[((j +  96) << 4) + p];
            #pragma unroll
            for (int r = 0; r < 8; r++) {
                float4 rv = rX4s[((rl0 + r) << 4) + cq];
                acc[r][0] = fmaf(rv.w, c0.w, fmaf(rv.z, c0.z, fmaf(rv.y, c0.y, fmaf(rv.x, c0.x, acc[r][0]))));
                acc[r][1] = fmaf(rv.w, c1.w, fmaf(rv.z, c1.z, fmaf(rv.y, c1.y, fmaf(rv.x, c1.x, acc[r][1]))));
                acc[r][2] = fmaf(rv.w, c2.w, fmaf(rv.z, c2.z, fmaf(rv.y, c2.y, fmaf(rv.x, c2.x, acc[r][2]))));
                acc[r][3] = fmaf(rv.w, c3.w, fmaf(rv.z, c3.z, fmaf(rv.y, c3.y, fmaf(rv.x, c3.x, acc[r][3]))));
            }
        }

        float xq0 = __ldg(&g_xx[b * NPTS + cb + j]);
        float xq1 = __ldg(&g_xx[b * NPTS + cb + j + 32]);
        float xq2 = __ldg(&g_xx[b * NPTS + cb + j + 64]);
        float xq3 = __ldg(&g_xx[b * NPTS + cb + j + 96]);

        #pragma unroll
        for (int r = 0; r < 8; r++) {
            float thr = __shfl_sync(FULLMASK, lv[r], KNN - 1);
            float cnd0 = fmaf(-2.f, acc[r][0], xq0);
            float cnd1 = fmaf(-2.f, acc[r][1], xq1);
            float cnd2 = fmaf(-2.f, acc[r][2], xq2);
            float cnd3 = fmaf(-2.f, acc[r][3], xq3);
            float rmax = fmaxf(fmaxf(cnd0, cnd1), fmaxf(cnd2, cnd3));
            if (__ballot_sync(FULLMASK, rmax > thr) == 0u) continue;

            #pragma unroll
            for (int q = 0; q < 4; q++) {
                float cand = (q == 0) ? cnd0 : (q == 1) ? cnd1 : (q == 2) ? cnd2 : cnd3;
                int   col  = cb + j + 32 * q;
                unsigned mask = __ballot_sync(FULLMASK, cand > thr);
                while (mask) {
                    int src = __ffs(mask) - 1; mask &= mask - 1;
                    float val = __shfl_sync(FULLMASK, cand, src);
                    int   ci  = __shfl_sync(FULLMASK, col,  src);
                    // stable insertion: pos = #elements >= val; pos>=20 -> no-op
                    unsigned ge = __ballot_sync(FULLMASK, inlist && (lv[r] >= val));
                    int pos = __popc(ge);
                    float pv = __shfl_up_sync(FULLMASK, lv[r], 1);
                    int   pi = __shfl_up_sync(FULLMASK, lidx[r], 1);
                    if (inlist) {
                        if (j == pos)     { lv[r] = val; lidx[r] = ci; }
                        else if (j > pos) { lv[r] = pv;  lidx[r] = pi; }
                    }
                }
                thr = __shfl_sync(FULLMASK, lv[r], KNN - 1);
            }
        }
    }

    #pragma unroll
    for (int r = 0; r < 8; r++) {
        int row = rowbase + rl0 + r;
        if (inlist) g_idx[(size_t)row * KNN + j] = lidx[r];
    }
}

// ---------------- K4: gather + BN stats + per-(row,o) max/min ----------------
__global__ void k_stats() {
    __shared__ int   sidx[32 * KNN];
    __shared__ float ssum[4][64];
    __shared__ float sssq[4][64];
    int tx = threadIdx.x, ty = threadIdx.y;
    int t = ty * 64 + tx;
    int rowbase = blockIdx.x * 32;
    int bb = (rowbase >> 11) << 11;

    for (int i = t; i < 32 * KNN; i += 256) sidx[i] = g_idx[(size_t)rowbase * KNN + i];
    __syncthreads();

    float sum = 0.f, ssq = 0.f;
    for (int ri = ty; ri < 32; ri += 4) {
        int row = rowbase + ri;
        float hcv = g_hc[(size_t)row * 64 + tx];
        float mx = NEG_INF, mn = -NEG_INF;
        #pragma unroll
        for (int k = 0; k < KNN; k++) {
            int jj = sidx[ri * KNN + k];
            float v = hcv + g_hn[(size_t)(bb + jj) * 64 + tx];
            sum += v; ssq = fmaf(v, v, ssq);
            mx = fmaxf(mx, v); mn = fminf(mn, v);
        }
        g_mmax[(size_t)row * 64 + tx] = mx;
        g_mmin[(size_t)row * 64 + tx] = mn;
    }
    ssum[ty][tx] = sum; sssq[ty][tx] = ssq;
    __syncthreads();
    if (ty == 0) {
        float s = ssum[0][tx] + ssum[1][tx] + ssum[2][tx] + ssum[3][tx];
        float q = sssq[0][tx] + sssq[1][tx] + sssq[2][tx] + sssq[3][tx];
        atomicAdd(&g_sum[tx],   (double)s);
        atomicAdd(&g_sumsq[tx], (double)q);
    }
}

// ---------------- K5: finalize BN scale/shift ----------------
__global__ void k_final(const float* __restrict__ gamma, const float* __restrict__ beta) {
    int o = threadIdx.x;
    if (o < ODIM) {
        double cnt  = (double)ROWS_TOTAL * KNN;
        double mean = g_sum[o] / cnt;
        double var  = g_sumsq[o] / cnt - mean * mean;
        float sc = gamma[o] * rsqrtf((float)var + 1e-5f);
        g_scale[o] = sc;
        g_shift[o] = beta[o] - (float)mean * sc;
    }
}

// ---------------- K6: apply affine + LeakyReLU + transpose to [B,O,N] ----------------
__global__ void k_out(float* __restrict__ out) {
    __shared__ float smt[64][65];
    int tx = threadIdx.x, ty = threadIdx.y;   // block (64,4)
    int nb = blockIdx.x * 64;
    int b  = blockIdx.y;
    float sc = g_scale[tx], sh = g_shift[tx];
    #pragma unroll
    for (int i = 0; i < 16; i++) {
        int nl = ty + 4 * i;
        size_t rowoff = (size_t)(b * NPTS + nb + nl) * 64 + tx;
        float m = (sc >= 0.f) ? g_mmax[rowoff] : g_mmin[rowoff];
        float y = fmaf(m, sc, sh);
        y = (y >= 0.f) ? y : 0.2f * y;
        smt[nl][tx] = y;
    }
    __syncthreads();
    #pragma unroll
    for (int i = 0; i < 16; i++) {
        int o = ty + 4 * i;
        out[((size_t)(b * 64 + o)) * NPTS + nb + tx] = smt[tx][o];
    }
}

extern "C" void kernel_launch(void* const* d_in, const int* in_sizes, int n_in,
                              void* d_out, int out_size) {
    const float* x     = (const float*)d_in[0];
    const float* W     = (const float*)d_in[1];
    const float* bias  = (const float*)d_in[2];
    const float* gamma = (const float*)d_in[3];
    const float* beta  = (const float*)d_in[4];
    float* out = (float*)d_out;

    k_zero<<<1, 64>>>();
    k_xx<<<ROWS_TOTAL / 4, 128>>>(x);
    k_hchn<<<ROWS_TOTAL / 32, 256, (128 * 17 + 32 * 16) * 16>>>(x, W, bias);
    k_topk<<<dim3(NPTS / 64, BATCH), 256>>>(x);
    k_stats<<<ROWS_TOTAL / 32, dim3(64, 4)>>>();
    k_final<<<1, 64>>>(gamma, beta);
    k_out<<<dim3(NPTS / 64, BATCH), dim3(64, 4)>>>(out);
}

// round 7
// speedup vs baseline: 1.0779x; 1.0292x over previous
#include <cuda_runtime.h>

#define BATCH 16
#define NPTS  2048
#define CDIM  64
#define ODIM  64
#define KNN   20
#define ROWS_TOTAL (BATCH*NPTS)   // 32768
#define NEG_INF (-3.402823466e38f)
#define FULLMASK 0xffffffffu

typedef unsigned long long ull;

// packed f32x2 helpers (sm_100+; ptxas never emits FFMA2 from C++)
#define LDS2(a0, a1, addr) \
    asm("ld.shared.v2.u64 {%0,%1},[%2];" : "=l"(a0), "=l"(a1) : "r"(addr))
#define FMA2(d, a, b) \
    asm("fma.rn.f32x2 %0, %1, %2, %0;" : "+l"(d) : "l"(a), "l"(b))
#define UNPACK2(lo, hi, v) \
    asm("mov.b64 {%0,%1}, %2;" : "=f"(lo), "=f"(hi) : "l"(v))

// ---------------- scratch (static device globals; no allocation) ----------------
__device__ float  g_xx[ROWS_TOTAL];
__device__ float  g_hc[ROWS_TOTAL*ODIM];
__device__ float  g_hn[ROWS_TOTAL*ODIM];
__device__ int    g_idx[ROWS_TOTAL*KNN];
__device__ float  g_mmax[ROWS_TOTAL*ODIM];
__device__ float  g_mmin[ROWS_TOTAL*ODIM];
__device__ double g_sum[ODIM];
__device__ double g_sumsq[ODIM];
__device__ float  g_scale[ODIM];
__device__ float  g_shift[ODIM];

// ---------------- K0: zero stats accumulators (graph replay safe) ----------------
__global__ void k_zero() {
    int t = threadIdx.x;
    if (t < ODIM) { g_sum[t] = 0.0; g_sumsq[t] = 0.0; }
}

// ---------------- K1: row squared norms ----------------
__global__ void k_xx(const float* __restrict__ x) {
    int row  = blockIdx.x * 4 + (threadIdx.x >> 5);
    int lane = threadIdx.x & 31;
    const float2* x2 = (const float2*)(x + (size_t)row * CDIM);
    float2 v = x2[lane];
    float s = v.x * v.x + v.y * v.y;
    #pragma unroll
    for (int o = 16; o; o >>= 1) s += __shfl_down_sync(FULLMASK, s, o);
    if (lane == 0) g_xx[row] = s;
}

// ---------------- K2: hc = x@W1^T + b, hn = x@W2^T  (32 rows/block) ----------------
__global__ void k_hchn(const float* __restrict__ x, const float* __restrict__ W,
                       const float* __restrict__ bias) {
    extern __shared__ float sm[];
    float4* Wt4 = (float4*)sm;          // [128*17]
    float4* rX4 = Wt4 + 128 * 17;       // [32*16]
    int t = threadIdx.x;
    int rowbase = blockIdx.x * 32;
    const float4* Wg4 = (const float4*)W;
    const float4* xg4 = (const float4*)x;

    #pragma unroll 2
    for (int li = t; li < 128 * 16; li += 256) {
        int cq = li & 15, p = li >> 4;
        Wt4[p * 17 + cq] = (p < 64) ? Wg4[p * 32 + cq] : Wg4[(p - 64) * 32 + 16 + cq];
    }
    for (int li = t; li < 32 * 16; li += 256) {
        int cq = li & 15, r = li >> 4;
        rX4[r * 16 + cq] = xg4[(size_t)(rowbase + r) * 16 + cq];
    }
    __syncthreads();

    int warp = t >> 5, j = t & 31;
    int rl0 = warp * 4;
    float acc[4][4];
    #pragma unroll
    for (int r = 0; r < 4; r++)
        #pragma unroll
        for (int q = 0; q < 4; q++) acc[r][q] = 0.f;

    #pragma unroll
    for (int cq = 0; cq < 16; cq++) {
        float4 c0 = Wt4[(j     ) * 17 + cq];
        float4 c1 = Wt4[(j + 32) * 17 + cq];
        float4 c2 = Wt4[(j + 64) * 17 + cq];
        float4 c3 = Wt4[(j + 96) * 17 + cq];
        #pragma unroll
        for (int r = 0; r < 4; r++) {
            float4 rv = rX4[(rl0 + r) * 16 + cq];
            acc[r][0] = fmaf(rv.w, c0.w, fmaf(rv.z, c0.z, fmaf(rv.y, c0.y, fmaf(rv.x, c0.x, acc[r][0]))));
            acc[r][1] = fmaf(rv.w, c1.w, fmaf(rv.z, c1.z, fmaf(rv.y, c1.y, fmaf(rv.x, c1.x, acc[r][1]))));
            acc[r][2] = fmaf(rv.w, c2.w, fmaf(rv.z, c2.z, fmaf(rv.y, c2.y, fmaf(rv.x, c2.x, acc[r][2]))));
            acc[r][3] = fmaf(rv.w, c3.w, fmaf(rv.z, c3.z, fmaf(rv.y, c3.y, fmaf(rv.x, c3.x, acc[r][3]))));
        }
    }
    #pragma unroll
    for (int q = 0; q < 4; q++) {
        int p = j + 32 * q;
        float bv = (p < 64) ? bias[p] : 0.f;
        #pragma unroll
        for (int r = 0; r < 4; r++) {
            int row = rowbase + rl0 + r;
            if (p < 64) g_hc[(size_t)row * 64 + p] = acc[r][q] + bv;
            else        g_hn[(size_t)row * 64 + (p - 64)] = acc[r][q];
        }
    }
}

// ---------------- K3: fused Gram + top-20 per row (FFMA2 col-pair packing) ----------------
// 256 threads = 8 warps, 64 rows/block (8 rows/warp), col tiles of 128.
// f32x2 accumulator halves hold two INDEPENDENT full dot products (cols c and
// c+64); each half accumulates over k in exactly the scalar order
// (k = 4cq..4cq+3 sequential) -> bitwise-identical distances to the R4 kernel.
// Columns in SMEM as interleaved pairs (x[c][k], x[c+64][k]) with XOR swizzle
// (conflict-free v2.u64 reads); rows stored DUPLICATED (x[r][k], x[r][k]) so
// the broadcast operand is a direct 16B load (zero packing movs).
// Top-20 list distributed across lanes (lane j holds element j, desc sorted;
// lanes 20..31 are overflow). Select-based insert (no ballot/popc in chain);
// stale threshold per 32-candidate batch (stale thr only admits candidates
// whose insertion position >= 20 -> no-op).
__global__ void __launch_bounds__(256, 3) k_topk(const float* __restrict__ x) {
    extern __shared__ ull smu[];
    ull* rDd = smu;              // [64*64] duplicated rows   (32 KB)
    ull* cPd = smu + 64 * 64;    // [64*64] col pairs swizzled (32 KB)
    float* rDf = (float*)rDd;
    float* cPf = (float*)cPd;

    int t = threadIdx.x;
    int b = blockIdx.y;
    int rowbase = b * NPTS + blockIdx.x * 64;
    const float4* xg4 = (const float4*)x;

    // build duplicated row tile (once)
    for (int li = t; li < 64 * 16; li += 256) {
        int cq = li & 15, r = li >> 4;
        float4 v = xg4[(size_t)(rowbase + r) * 16 + cq];
        int base = (r * 64 + cq * 4) * 2;
        rDf[base + 0] = v.x; rDf[base + 1] = v.x;
        rDf[base + 2] = v.y; rDf[base + 3] = v.y;
        rDf[base + 4] = v.z; rDf[base + 5] = v.z;
        rDf[base + 6] = v.w; rDf[base + 7] = v.w;
    }

    int warp = t >> 5, j = t & 31;
    int rl0 = warp * 8;

    unsigned sb     = (unsigned)__cvta_generic_to_shared(smu);
    unsigned rWbase = sb + (unsigned)(rl0 * 512);           // this warp's rows
    unsigned cp0    = sb + 64u * 64u * 8u + (unsigned)(j * 512);
    unsigned cp1    = cp0 + 32u * 512u;

    float lv[8]; int lidx[8];
    #pragma unroll
    for (int r = 0; r < 8; r++) { lv[r] = NEG_INF; lidx[r] = 0; }

    for (int ct = 0; ct < 16; ct++) {
        int cb = ct * 128;
        __syncthreads();
        // build col-pair tile: cP[p][k] = (x[cb+p][k], x[cb+p+64][k]), swizzled
        for (int li = t; li < 128 * 16; li += 256) {
            int cq = li & 15, col = li >> 4;
            float4 v = xg4[(size_t)(b * NPTS + cb + col) * 16 + cq];
            int p = col & 63, half = col >> 6;
            int pb = p * 64, px = p & 31;
            int s0 = (2 * cq) ^ px, s1 = (2 * cq + 1) ^ px;
            cPf[(pb + s0 * 2    ) * 2 + half] = v.x;
            cPf[(pb + s0 * 2 + 1) * 2 + half] = v.y;
            cPf[(pb + s1 * 2    ) * 2 + half] = v.z;
            cPf[(pb + s1 * 2 + 1) * 2 + half] = v.w;
        }
        __syncthreads();

        ull A[8][2];
        #pragma unroll
        for (int r = 0; r < 8; r++) { A[r][0] = 0ull; A[r][1] = 0ull; }

        #pragma unroll 2
        for (int cq = 0; cq < 16; cq++) {
            #pragma unroll
            for (int m = 0; m < 2; m++) {
                unsigned slot = (unsigned)(((2 * cq + m) ^ j) * 16);
                ull a0, a1, b0, b1;
                LDS2(a0, a1, cp0 + slot);       // cols (cb+j,    cb+j+64) : k, k+1
                LDS2(b0, b1, cp1 + slot);       // cols (cb+j+32, cb+j+96) : k, k+1
                unsigned rof = rWbase + (unsigned)(cq * 32 + m * 16);
                #pragma unroll
                for (int r = 0; r < 8; r++) {
                    ull r0, r1;
                    LDS2(r0, r1, rof + (unsigned)(r * 512));  // (x_r_k,x_r_k),(x_r_k1,x_r_k1)
                    FMA2(A[r][0], a0, r0); FMA2(A[r][1], b0, r0);
                    FMA2(A[r][0], a1, r1); FMA2(A[r][1], b1, r1);
                }
            }
        }

        float xq0 = __ldg(&g_xx[b * NPTS + cb + j]);
        float xq1 = __ldg(&g_xx[b * NPTS + cb + j + 32]);
        float xq2 = __ldg(&g_xx[b * NPTS + cb + j + 64]);
        float xq3 = __ldg(&g_xx[b * NPTS + cb + j + 96]);

        #pragma unroll
        for (int r = 0; r < 8; r++) {
            float lo0, hi0, lo1, hi1;
            UNPACK2(lo0, hi0, A[r][0]);
            UNPACK2(lo1, hi1, A[r][1]);
            float cnd0 = fmaf(-2.f, lo0, xq0);
            float cnd1 = fmaf(-2.f, lo1, xq1);
            float cnd2 = fmaf(-2.f, hi0, xq2);
            float cnd3 = fmaf(-2.f, hi1, xq3);
            float thr = __shfl_sync(FULLMASK, lv[r], KNN - 1);
            float rmax = fmaxf(fmaxf(cnd0, cnd1), fmaxf(cnd2, cnd3));
            if (__ballot_sync(FULLMASK, rmax > thr) == 0u) continue;

            #pragma unroll
            for (int q = 0; q < 4; q++) {
                float cand = (q == 0) ? cnd0 : (q == 1) ? cnd1 : (q == 2) ? cnd2 : cnd3;
                int   col  = cb + j + 32 * q;
                unsigned mask = __ballot_sync(FULLMASK, cand > thr);
                while (mask) {
                    int src = __ffs(mask) - 1; mask &= mask - 1;
                    float val = __shfl_sync(FULLMASK, cand, src);
                    int   ci  = __shfl_sync(FULLMASK, col,  src);
                    float pv  = __shfl_up_sync(FULLMASK, lv[r], 1);
                    int   pi  = __shfl_up_sync(FULLMASK, lidx[r], 1);
                    bool keep = (lv[r] >= val);
                    bool prevkeep = (j == 0) || (pv >= val);
                    if (!keep) {
                        lv[r]   = prevkeep ? val : pv;
                        lidx[r] = prevkeep ? ci  : pi;
                    }
                }
                thr = __shfl_sync(FULLMASK, lv[r], KNN - 1);
            }
        }
    }

    #pragma unroll
    for (int r = 0; r < 8; r++) {
        int row = rowbase + rl0 + r;
        if (j < KNN) g_idx[(size_t)row * KNN + j] = lidx[r];
    }
}

// ---------------- K4: gather + BN stats + per-(row,o) max/min ----------------
__global__ void k_stats() {
    __shared__ int   sidx[32 * KNN];
    __shared__ float ssum[4][64];
    __shared__ float sssq[4][64];
    int tx = threadIdx.x, ty = threadIdx.y;
    int t = ty * 64 + tx;
    int rowbase = blockIdx.x * 32;
    int bb = (rowbase >> 11) << 11;

    for (int i = t; i < 32 * KNN; i += 256) sidx[i] = g_idx[(size_t)rowbase * KNN + i];
    __syncthreads();

    float sum = 0.f, ssq = 0.f;
    for (int ri = ty; ri < 32; ri += 4) {
        int row = rowbase + ri;
        float hcv = g_hc[(size_t)row * 64 + tx];
        float mx = NEG_INF, mn = -NEG_INF;
        #pragma unroll
        for (int k = 0; k < KNN; k++) {
            int jj = sidx[ri * KNN + k];
            float v = hcv + g_hn[(size_t)(bb + jj) * 64 + tx];
            sum += v; ssq = fmaf(v, v, ssq);
            mx = fmaxf(mx, v); mn = fminf(mn, v);
        }
        g_mmax[(size_t)row * 64 + tx] = mx;
        g_mmin[(size_t)row * 64 + tx] = mn;
    }
    ssum[ty][tx] = sum; sssq[ty][tx] = ssq;
    __syncthreads();
    if (ty == 0) {
        float s = ssum[0][tx] + ssum[1][tx] + ssum[2][tx] + ssum[3][tx];
        float q = sssq[0][tx] + sssq[1][tx] + sssq[2][tx] + sssq[3][tx];
        atomicAdd(&g_sum[tx],   (double)s);
        atomicAdd(&g_sumsq[tx], (double)q);
    }
}

// ---------------- K5: finalize BN scale/shift ----------------
__global__ void k_final(const float* __restrict__ gamma, const float* __restrict__ beta) {
    int o = threadIdx.x;
    if (o < ODIM) {
        double cnt  = (double)ROWS_TOTAL * KNN;
        double mean = g_sum[o] / cnt;
        double var  = g_sumsq[o] / cnt - mean * mean;
        float sc = gamma[o] * rsqrtf((float)var + 1e-5f);
        g_scale[o] = sc;
        g_shift[o] = beta[o] - (float)mean * sc;
    }
}

// ---------------- K6: apply affine + LeakyReLU + transpose to [B,O,N] ----------------
__global__ void k_out(float* __restrict__ out) {
    __shared__ float smt[64][65];
    int tx = threadIdx.x, ty = threadIdx.y;   // block (64,4)
    int nb = blockIdx.x * 64;
    int b  = blockIdx.y;
    float sc = g_scale[tx], sh = g_shift[tx];
    #pragma unroll
    for (int i = 0; i < 16; i++) {
        int nl = ty + 4 * i;
        size_t rowoff = (size_t)(b * NPTS + nb + nl) * 64 + tx;
        float m = (sc >= 0.f) ? g_mmax[rowoff] : g_mmin[rowoff];
        float y = fmaf(m, sc, sh);
        y = (y >= 0.f) ? y : 0.2f * y;
        smt[nl][tx] = y;
    }
    __syncthreads();
    #pragma unroll
    for (int i = 0; i < 16; i++) {
        int o = ty + 4 * i;
        out[((size_t)(b * 64 + o)) * NPTS + nb + tx] = smt[tx][o];
    }
}

extern "C" void kernel_launch(void* const* d_in, const int* in_sizes, int n_in,
                              void* d_out, int out_size) {
    const float* x     = (const float*)d_in[0];
    const float* W     = (const float*)d_in[1];
    const float* bias  = (const float*)d_in[2];
    const float* gamma = (const float*)d_in[3];
    const float* beta  = (const float*)d_in[4];
    float* out = (float*)d_out;

    static int attr_done = 0;
    if (!attr_done) {
        cudaFuncSetAttribute(k_topk, cudaFuncAttributeMaxDynamicSharedMemorySize, 65536);
        attr_done = 1;
    }

    k_zero<<<1, 64>>>();
    k_xx<<<ROWS_TOTAL / 4, 128>>>(x);
    k_hchn<<<ROWS_TOTAL / 32, 256, (128 * 17 + 32 * 16) * 16>>>(x, W, bias);
    k_topk<<<dim3(NPTS / 64, BATCH), 256, 65536>>>(x);
    k_stats<<<ROWS_TOTAL / 32, dim3(64, 4)>>>();
    k_final<<<1, 64>>>(gamma, beta);
    k_out<<<dim3(NPTS / 64, BATCH), dim3(64, 4)>>>(out);
}

// round 8
// speedup vs baseline: 1.2264x; 1.1378x over previous
#include <cuda_runtime.h>

#define BATCH 16
#define NPTS  2048
#define CDIM  64
#define ODIM  64
#define KNN   20
#define ROWS_TOTAL (BATCH*NPTS)   // 32768
#define NEG_INF (-3.402823466e38f)
#define FULLMASK 0xffffffffu

typedef unsigned long long ull;

// packed f32x2 helpers (sm_100+; ptxas never emits FFMA2 from C++)
#define LDS2(a0, a1, addr) \
    asm("ld.shared.v2.u64 {%0,%1},[%2];" : "=l"(a0), "=l"(a1) : "r"(addr))
#define FMA2(d, a, b) \
    asm("fma.rn.f32x2 %0, %1, %2, %0;" : "+l"(d) : "l"(a), "l"(b))
#define UNPACK2(lo, hi, v) \
    asm("mov.b64 {%0,%1}, %2;" : "=f"(lo), "=f"(hi) : "l"(v))

// ---------------- scratch (static device globals; no allocation) ----------------
__device__ float  g_xx[ROWS_TOTAL];
__device__ float  g_hc[ROWS_TOTAL*ODIM];
__device__ float  g_hn[ROWS_TOTAL*ODIM];
__device__ int    g_idx[ROWS_TOTAL*KNN];
__device__ float  g_mmax[ROWS_TOTAL*ODIM];
__device__ float  g_mmin[ROWS_TOTAL*ODIM];
__device__ double g_sum[ODIM];
__device__ double g_sumsq[ODIM];
__device__ float  g_scale[ODIM];
__device__ float  g_shift[ODIM];

// ---------------- K0: zero stats accumulators (graph replay safe) ----------------
__global__ void k_zero() {
    int t = threadIdx.x;
    if (t < ODIM) { g_sum[t] = 0.0; g_sumsq[t] = 0.0; }
}

// ---------------- K1: row squared norms ----------------
__global__ void k_xx(const float* __restrict__ x) {
    int row  = blockIdx.x * 4 + (threadIdx.x >> 5);
    int lane = threadIdx.x & 31;
    const float2* x2 = (const float2*)(x + (size_t)row * CDIM);
    float2 v = x2[lane];
    float s = v.x * v.x + v.y * v.y;
    #pragma unroll
    for (int o = 16; o; o >>= 1) s += __shfl_down_sync(FULLMASK, s, o);
    if (lane == 0) g_xx[row] = s;
}

// ---------------- K2: hc = x@W1^T + b, hn = x@W2^T  (32 rows/block) ----------------
__global__ void k_hchn(const float* __restrict__ x, const float* __restrict__ W,
                       const float* __restrict__ bias) {
    extern __shared__ float sm[];
    float4* Wt4 = (float4*)sm;          // [128*17]
    float4* rX4 = Wt4 + 128 * 17;       // [32*16]
    int t = threadIdx.x;
    int rowbase = blockIdx.x * 32;
    const float4* Wg4 = (const float4*)W;
    const float4* xg4 = (const float4*)x;

    #pragma unroll 2
    for (int li = t; li < 128 * 16; li += 256) {
        int cq = li & 15, p = li >> 4;
        Wt4[p * 17 + cq] = (p < 64) ? Wg4[p * 32 + cq] : Wg4[(p - 64) * 32 + 16 + cq];
    }
    for (int li = t; li < 32 * 16; li += 256) {
        int cq = li & 15, r = li >> 4;
        rX4[r * 16 + cq] = xg4[(size_t)(rowbase + r) * 16 + cq];
    }
    __syncthreads();

    int warp = t >> 5, j = t & 31;
    int rl0 = warp * 4;
    float acc[4][4];
    #pragma unroll
    for (int r = 0; r < 4; r++)
        #pragma unroll
        for (int q = 0; q < 4; q++) acc[r][q] = 0.f;

    #pragma unroll
    for (int cq = 0; cq < 16; cq++) {
        float4 c0 = Wt4[(j     ) * 17 + cq];
        float4 c1 = Wt4[(j + 32) * 17 + cq];
        float4 c2 = Wt4[(j + 64) * 17 + cq];
        float4 c3 = Wt4[(j + 96) * 17 + cq];
        #pragma unroll
        for (int r = 0; r < 4; r++) {
            float4 rv = rX4[(rl0 + r) * 16 + cq];
            acc[r][0] = fmaf(rv.w, c0.w, fmaf(rv.z, c0.z, fmaf(rv.y, c0.y, fmaf(rv.x, c0.x, acc[r][0]))));
            acc[r][1] = fmaf(rv.w, c1.w, fmaf(rv.z, c1.z, fmaf(rv.y, c1.y, fmaf(rv.x, c1.x, acc[r][1]))));
            acc[r][2] = fmaf(rv.w, c2.w, fmaf(rv.z, c2.z, fmaf(rv.y, c2.y, fmaf(rv.x, c2.x, acc[r][2]))));
            acc[r][3] = fmaf(rv.w, c3.w, fmaf(rv.z, c3.z, fmaf(rv.y, c3.y, fmaf(rv.x, c3.x, acc[r][3]))));
        }
    }
    #pragma unroll
    for (int q = 0; q < 4; q++) {
        int p = j + 32 * q;
        float bv = (p < 64) ? bias[p] : 0.f;
        #pragma unroll
        for (int r = 0; r < 4; r++) {
            int row = rowbase + rl0 + r;
            if (p < 64) g_hc[(size_t)row * 64 + p] = acc[r][q] + bv;
            else        g_hn[(size_t)row * 64 + (p - 64)] = acc[r][q];
        }
    }
}

// ---------------- K3: fused Gram + top-20 per row (FFMA2, 4 rows/warp) ----------------
// 256 threads = 8 warps, 32 rows/block (4 rows/warp), col tiles of 128.
// f32x2 accumulator halves hold two INDEPENDENT full dot products (cols c and
// c+64); each half accumulates over k in exactly the scalar order
// (k = 4cq..4cq+3 sequential) -> bitwise-identical distances to the R4 kernel.
// Columns in SMEM as interleaved pairs (x[c][k], x[c+64][k]) with XOR swizzle;
// rows stored DUPLICATED (x[r][k], x[r][k]) so the broadcast operand is a
// direct 16B load (zero packing movs). 48KB static SMEM -> 4 CTAs/SM.
// Top-20 list distributed across lanes (lane j holds element j, desc sorted;
// lanes 20..31 overflow). Select-based insert; stale threshold per batch
// (stale thr only admits candidates whose insertion pos >= 20 -> no-op).
__global__ void __launch_bounds__(256, 4) k_topk(const float* __restrict__ x) {
    __shared__ ull rDd[32 * 64];   // duplicated rows   (16 KB)
    __shared__ ull cPd[64 * 64];   // col pairs swizzled (32 KB)
    float* rDf = (float*)rDd;
    float* cPf = (float*)cPd;

    int t = threadIdx.x;
    int b = blockIdx.y;
    int rowbase = b * NPTS + blockIdx.x * 32;
    const float4* xg4 = (const float4*)x;

    // build duplicated row tile (once): rD[r][k] = (x[r][k], x[r][k])
    for (int li = t; li < 32 * 16; li += 256) {
        int cq = li & 15, r = li >> 4;
        float4 v = xg4[(size_t)(rowbase + r) * 16 + cq];
        int base = (r * 64 + cq * 4) * 2;
        rDf[base + 0] = v.x; rDf[base + 1] = v.x;
        rDf[base + 2] = v.y; rDf[base + 3] = v.y;
        rDf[base + 4] = v.z; rDf[base + 5] = v.z;
        rDf[base + 6] = v.w; rDf[base + 7] = v.w;
    }

    int warp = t >> 5, j = t & 31;
    int rl0 = warp * 4;

    unsigned sbr = (unsigned)__cvta_generic_to_shared(rDd);
    unsigned sbc = (unsigned)__cvta_generic_to_shared(cPd);
    unsigned rWbase = sbr + (unsigned)(rl0 * 512);   // this warp's 4 rows
    unsigned cp0 = sbc + (unsigned)(j * 512);        // pair (j, j+64)
    unsigned cp1 = cp0 + 32u * 512u;                 // pair (j+32, j+96)

    float lv[4]; int lidx[4];
    #pragma unroll
    for (int r = 0; r < 4; r++) { lv[r] = NEG_INF; lidx[r] = 0; }

    for (int ct = 0; ct < 16; ct++) {
        int cb = ct * 128;
        __syncthreads();
        // build col-pair tile: cP[p][kp] = (x[cb+p][*], x[cb+p+64][*]), swizzled
        for (int li = t; li < 128 * 16; li += 256) {
            int cq = li & 15, col = li >> 4;
            float4 v = xg4[(size_t)(b * NPTS + cb + col) * 16 + cq];
            int p = col & 63, half = col >> 6;
            int pb = p * 64, px = p & 31;
            int s0 = (2 * cq) ^ px, s1 = (2 * cq + 1) ^ px;
            cPf[(pb + s0 * 2    ) * 2 + half] = v.x;
            cPf[(pb + s0 * 2 + 1) * 2 + half] = v.y;
            cPf[(pb + s1 * 2    ) * 2 + half] = v.z;
            cPf[(pb + s1 * 2 + 1) * 2 + half] = v.w;
        }
        __syncthreads();

        ull A[4][2];
        #pragma unroll
        for (int r = 0; r < 4; r++) { A[r][0] = 0ull; A[r][1] = 0ull; }

        #pragma unroll 4
        for (int cq = 0; cq < 16; cq++) {
            #pragma unroll
            for (int m = 0; m < 2; m++) {
                unsigned slot = (unsigned)(((2 * cq + m) ^ j) * 16);
                ull a0, a1, b0, b1;
                LDS2(a0, a1, cp0 + slot);   // cols (cb+j,    cb+j+64) : k, k+1
                LDS2(b0, b1, cp1 + slot);   // cols (cb+j+32, cb+j+96) : k, k+1
                unsigned rof = rWbase + (unsigned)((2 * cq + m) * 16);
                #pragma unroll
                for (int r = 0; r < 4; r++) {
                    ull r0, r1;
                    LDS2(r0, r1, rof + (unsigned)(r * 512));  // (x_rk,x_rk),(x_rk1,x_rk1)
                    FMA2(A[r][0], a0, r0); FMA2(A[r][1], b0, r0);
                    FMA2(A[r][0], a1, r1); FMA2(A[r][1], b1, r1);
                }
            }
        }

        float xq0 = __ldg(&g_xx[b * NPTS + cb + j]);
        float xq1 = __ldg(&g_xx[b * NPTS + cb + j + 32]);
        float xq2 = __ldg(&g_xx[b * NPTS + cb + j + 64]);
        float xq3 = __ldg(&g_xx[b * NPTS + cb + j + 96]);

        #pragma unroll
        for (int r = 0; r < 4; r++) {
            float lo0, hi0, lo1, hi1;
            UNPACK2(lo0, hi0, A[r][0]);
            UNPACK2(lo1, hi1, A[r][1]);
            float cnd0 = fmaf(-2.f, lo0, xq0);
            float cnd1 = fmaf(-2.f, lo1, xq1);
            float cnd2 = fmaf(-2.f, hi0, xq2);
            float cnd3 = fmaf(-2.f, hi1, xq3);
            float thr = __shfl_sync(FULLMASK, lv[r], KNN - 1);
            float rmax = fmaxf(fmaxf(cnd0, cnd1), fmaxf(cnd2, cnd3));
            if (__ballot_sync(FULLMASK, rmax > thr) == 0u) continue;

            #pragma unroll
            for (int q = 0; q < 4; q++) {
                float cand = (q == 0) ? cnd0 : (q == 1) ? cnd1 : (q == 2) ? cnd2 : cnd3;
                int   col  = cb + j + 32 * q;
                unsigned mask = __ballot_sync(FULLMASK, cand > thr);
                while (mask) {
                    int src = __ffs(mask) - 1; mask &= mask - 1;
                    float val = __shfl_sync(FULLMASK, cand, src);
                    int   ci  = __shfl_sync(FULLMASK, col,  src);
                    float pv  = __shfl_up_sync(FULLMASK, lv[r], 1);
                    int   pi  = __shfl_up_sync(FULLMASK, lidx[r], 1);
                    bool keep = (lv[r] >= val);
                    bool prevkeep = (j == 0) || (pv >= val);
                    if (!keep) {
                        lv[r]   = prevkeep ? val : pv;
                        lidx[r] = prevkeep ? ci  : pi;
                    }
                }
                thr = __shfl_sync(FULLMASK, lv[r], KNN - 1);
            }
        }
    }

    #pragma unroll
    for (int r = 0; r < 4; r++) {
        int row = rowbase + rl0 + r;
        if (j < KNN) g_idx[(size_t)row * KNN + j] = lidx[r];
    }
}

// ---------------- K4: gather + BN stats + per-(row,o) max/min ----------------
__global__ void k_stats() {
    __shared__ int   sidx[32 * KNN];
    __shared__ float ssum[4][64];
    __shared__ float sssq[4][64];
    int tx = threadIdx.x, ty = threadIdx.y;
    int t = ty * 64 + tx;
    int rowbase = blockIdx.x * 32;
    int bb = (rowbase >> 11) << 11;

    for (int i = t; i < 32 * KNN; i += 256) sidx[i] = g_idx[(size_t)rowbase * KNN + i];
    __syncthreads();

    float sum = 0.f, ssq = 0.f;
    for (int ri = ty; ri < 32; ri += 4) {
        int row = rowbase + ri;
        float hcv = g_hc[(size_t)row * 64 + tx];
        float mx = NEG_INF, mn = -NEG_INF;
        #pragma unroll
        for (int k = 0; k < KNN; k++) {
            int jj = sidx[ri * KNN + k];
            float v = hcv + g_hn[(size_t)(bb + jj) * 64 + tx];
            sum += v; ssq = fmaf(v, v, ssq);
            mx = fmaxf(mx, v); mn = fminf(mn, v);
        }
        g_mmax[(size_t)row * 64 + tx] = mx;
        g_mmin[(size_t)row * 64 + tx] = mn;
    }
    ssum[ty][tx] = sum; sssq[ty][tx] = ssq;
    __syncthreads();
    if (ty == 0) {
        float s = ssum[0][tx] + ssum[1][tx] + ssum[2][tx] + ssum[3][tx];
        float q = sssq[0][tx] + sssq[1][tx] + sssq[2][tx] + sssq[3][tx];
        atomicAdd(&g_sum[tx],   (double)s);
        atomicAdd(&g_sumsq[tx], (double)q);
    }
}

// ---------------- K5: finalize BN scale/shift ----------------
__global__ void k_final(const float* __restrict__ gamma, const float* __restrict__ beta) {
    int o = threadIdx.x;
    if (o < ODIM) {
        double cnt  = (double)ROWS_TOTAL * KNN;
        double mean = g_sum[o] / cnt;
        double var  = g_sumsq[o] / cnt - mean * mean;
        float sc = gamma[o] * rsqrtf((float)var + 1e-5f);
        g_scale[o] = sc;
        g_shift[o] = beta[o] - (float)mean * sc;
    }
}

// ---------------- K6: apply affine + LeakyReLU + transpose to [B,O,N] ----------------
__global__ void k_out(float* __restrict__ out) {
    __shared__ float smt[64][65];
    int tx = threadIdx.x, ty = threadIdx.y;   // block (64,4)
    int nb = blockIdx.x * 64;
    int b  = blockIdx.y;
    float sc = g_scale[tx], sh = g_shift[tx];
    #pragma unroll
    for (int i = 0; i < 16; i++) {
        int nl = ty + 4 * i;
        size_t rowoff = (size_t)(b * NPTS + nb + nl) * 64 + tx;
        float m = (sc >= 0.f) ? g_mmax[rowoff] : g_mmin[rowoff];
        float y = fmaf(m, sc, sh);
        y = (y >= 0.f) ? y : 0.2f * y;
        smt[nl][tx] = y;
    }
    __syncthreads();
    #pragma unroll
    for (int i = 0; i < 16; i++) {
        int o = ty + 4 * i;
        out[((size_t)(b * 64 + o)) * NPTS + nb + tx] = smt[tx][o];
    }
}

extern "C" void kernel_launch(void* const* d_in, const int* in_sizes, int n_in,
                              void* d_out, int out_size) {
    const float* x     = (const float*)d_in[0];
    const float* W     = (const float*)d_in[1];
    const float* bias  = (const float*)d_in[2];
    const float* gamma = (const float*)d_in[3];
    const float* beta  = (const float*)d_in[4];
    float* out = (float*)d_out;

    k_zero<<<1, 64>>>();
    k_xx<<<ROWS_TOTAL / 4, 128>>>(x);
    k_hchn<<<ROWS_TOTAL / 32, 256, (128 * 17 + 32 * 16) * 16>>>(x, W, bias);
    k_topk<<<dim3(NPTS / 32, BATCH), 256>>>(x);
    k_stats<<<ROWS_TOTAL / 32, dim3(64, 4)>>>();
    k_final<<<1, 64>>>(gamma, beta);
    k_out<<<dim3(NPTS / 64, BATCH), dim3(64, 4)>>>(out);
}